// round 2
// baseline (speedup 1.0000x reference)
#include <cuda_runtime.h>
#include <cuda_bf16.h>

// CrossNetwork (DCN-v1), closed form:
//   x_i = c_i * input + d_i
//   d_{i+1} = d_i + b_i ; e_i = d_i.w_i ; S_i = input.w_i (per-row)
//   c_{i+1} = c_i*(1+S_i) + e_i, c_0 = 1 ; out = c_L*input + d_L
//
// R2: W/d_L register-resident, grid-stride rows, per-CTA prologue (no 2nd
// launch), 1 barrier/row via double-buffered cross-warp shuffle reduction,
// next-row input prefetch. L1 traffic/row: 9KB -> 2KB.

#define D    1024
#define L    6
#define TPB  256          // 8 warps; thread t owns columns [4t, 4t+4)
#define NW   (TPB / 32)

__global__ void __launch_bounds__(TPB) cross_fused(const float* __restrict__ input,
                                                   const float* __restrict__ W,
                                                   const float* __restrict__ b,
                                                   float* __restrict__ out,
                                                   int B) {
    const int t = threadIdx.x;
    const int lane = t & 31, warp = t >> 5;
    const unsigned FULL = 0xFFFFFFFFu;

    __shared__ float red[2][L][NW];

    // ---- Register-resident W slice for this thread's 4 columns ----
    float4 w4[L];
    #pragma unroll
    for (int l = 0; l < L; ++l)
        w4[l] = __ldg(reinterpret_cast<const float4*>(W + l * D) + t);

    // ---- Per-CTA prologue: d_L (vector, per-thread float4) and e_l (scalars) ----
    float4 d4 = make_float4(0.f, 0.f, 0.f, 0.f);
    float pe[L];
    #pragma unroll
    for (int l = 0; l < L; ++l) {
        pe[l] = d4.x * w4[l].x + d4.y * w4[l].y + d4.z * w4[l].z + d4.w * w4[l].w;
        float4 b4 = __ldg(reinterpret_cast<const float4*>(b + l * D) + t);
        d4.x += b4.x; d4.y += b4.y; d4.z += b4.z; d4.w += b4.w;
    }
    // block-reduce pe[] into e[] (buffer 0), identical order in every CTA
    #pragma unroll
    for (int l = 0; l < L; ++l) {
        float v = pe[l];
        #pragma unroll
        for (int o = 16; o > 0; o >>= 1) v += __shfl_xor_sync(FULL, v, o);
        if (lane == 0) red[0][l][warp] = v;
    }
    __syncthreads();
    float e[L];
    #pragma unroll
    for (int l = 0; l < L; ++l) {
        float v = (lane < NW) ? red[0][l][lane] : 0.f;
        v += __shfl_xor_sync(FULL, v, 4);
        v += __shfl_xor_sync(FULL, v, 2);
        v += __shfl_xor_sync(FULL, v, 1);
        e[l] = __shfl_sync(FULL, v, 0);
    }

    // ---- Grid-stride row loop with input prefetch ----
    const float4* in4  = reinterpret_cast<const float4*>(input);
    float4*       out4 = reinterpret_cast<float4*>(out);
    const int stride = gridDim.x;
    const int D4 = D / 4;

    int row = blockIdx.x;
    int p = 1;                                   // parity (prologue used 0)
    float4 xi;
    if (row < B) xi = in4[(size_t)row * D4 + t];

    for (; row < B; row += stride, p ^= 1) {
        // prefetch next row while this row reduces
        const int nrow = row + stride;
        float4 xn;
        if (nrow < B) xn = in4[(size_t)nrow * D4 + t];

        // 6 simultaneous dot partials against register W
        float acc[L];
        #pragma unroll
        for (int l = 0; l < L; ++l)
            acc[l] = xi.x * w4[l].x + xi.y * w4[l].y + xi.z * w4[l].z + xi.w * w4[l].w;

        // warp reduce, stash per-warp partials (double-buffered)
        #pragma unroll
        for (int l = 0; l < L; ++l) {
            float v = acc[l];
            #pragma unroll
            for (int o = 16; o > 0; o >>= 1) v += __shfl_xor_sync(FULL, v, o);
            if (lane == 0) red[p][l][warp] = v;
        }
        __syncthreads();

        // every warp combines the NW partials itself (broadcast LDS, no 2nd barrier)
        float c = 1.0f;
        #pragma unroll
        for (int l = 0; l < L; ++l) {
            float v = (lane < NW) ? red[p][l][lane] : 0.f;
            v += __shfl_xor_sync(FULL, v, 4);
            v += __shfl_xor_sync(FULL, v, 2);
            v += __shfl_xor_sync(FULL, v, 1);
            float S = __shfl_sync(FULL, v, 0);
            c = fmaf(c, 1.0f + S, e[l]);
        }

        float4 o;
        o.x = fmaf(c, xi.x, d4.x);
        o.y = fmaf(c, xi.y, d4.y);
        o.z = fmaf(c, xi.z, d4.z);
        o.w = fmaf(c, xi.w, d4.w);
        out4[(size_t)row * D4 + t] = o;

        xi = xn;
    }
}

extern "C" void kernel_launch(void* const* d_in, const int* in_sizes, int n_in,
                              void* d_out, int out_size) {
    const float* input = (const float*)d_in[0];   // [B, D]
    const float* W     = (const float*)d_in[1];   // [L, D]
    const float* b     = (const float*)d_in[2];   // [L, D]
    float* out = (float*)d_out;

    int B = in_sizes[0] / D;

    int grid = 148 * 8;                // ~14 rows per CTA at B=16384
    if (grid > B) grid = B;

    cross_fused<<<grid, TPB>>>(input, W, b, out, B);
}

// round 3
// speedup vs baseline: 1.6250x; 1.6250x over previous
#include <cuda_runtime.h>
#include <cuda_bf16.h>

// CrossNetwork (DCN-v1), closed form:
//   x_i = c_i * input + d_i
//   d_{i+1} = d_i + b_i ; e_i = d_i.w_i ; S_i = input.w_i (per-row)
//   c_{i+1} = c_i*(1+S_i) + e_i, c_0 = 1 ; out = c_L*input + d_L
//
// R3: MIO-op diet. TPB=128 (4 warps), 8 cols/thread, W register-resident.
// Per row: 30 shfl warp-reduce + 1 packed STS/warp + 1 barrier +
// (1 LDS + 8 shfl) cross-warp combine. ~160 MIO ops/row vs ~530 in R2.

#define D    1024
#define L    6
#define TPB  128
#define NW   (TPB / 32)      // 4 warps -> L*NW = 24 partials (fits one warp)

__device__ __forceinline__ float pick6(const float a[L], int i) {
    float s = a[0];
    s = (i == 1) ? a[1] : s;
    s = (i == 2) ? a[2] : s;
    s = (i == 3) ? a[3] : s;
    s = (i == 4) ? a[4] : s;
    s = (i == 5) ? a[5] : s;
    return s;
}

__global__ void __launch_bounds__(TPB, 5) cross_fused(const float* __restrict__ input,
                                                      const float* __restrict__ W,
                                                      const float* __restrict__ b,
                                                      float* __restrict__ out,
                                                      int B) {
    const int t = threadIdx.x;
    const int lane = t & 31, warp = t >> 5;
    const unsigned FULL = 0xFFFFFFFFu;

    __shared__ float red[2][32];          // flat: index = layer*NW + warp

    // ---- W slice for this thread's 8 columns (2 float4 per layer) ----
    float4 wa[L], wb[L];
    #pragma unroll
    for (int l = 0; l < L; ++l) {
        wa[l] = __ldg(reinterpret_cast<const float4*>(W + l * D) + 2 * t);
        wb[l] = __ldg(reinterpret_cast<const float4*>(W + l * D) + 2 * t + 1);
    }

    // ---- Per-CTA prologue: d_L (per-thread 8 floats) and e_l (scalars) ----
    float4 da = make_float4(0.f, 0.f, 0.f, 0.f);
    float4 db = make_float4(0.f, 0.f, 0.f, 0.f);
    float pe[L];
    #pragma unroll
    for (int l = 0; l < L; ++l) {
        pe[l] = da.x * wa[l].x + da.y * wa[l].y + da.z * wa[l].z + da.w * wa[l].w
              + db.x * wb[l].x + db.y * wb[l].y + db.z * wb[l].z + db.w * wb[l].w;
        float4 ba = __ldg(reinterpret_cast<const float4*>(b + l * D) + 2 * t);
        float4 bb = __ldg(reinterpret_cast<const float4*>(b + l * D) + 2 * t + 1);
        da.x += ba.x; da.y += ba.y; da.z += ba.z; da.w += ba.w;
        db.x += bb.x; db.y += bb.y; db.z += bb.z; db.w += bb.w;
    }
    #pragma unroll
    for (int l = 0; l < L; ++l) {
        #pragma unroll
        for (int o = 16; o > 0; o >>= 1) pe[l] += __shfl_xor_sync(FULL, pe[l], o);
    }
    if (lane < L) red[0][lane * NW + warp] = pick6(pe, lane);
    __syncthreads();
    float e[L];
    {
        float v = (lane < L * NW) ? red[0][lane] : 0.f;
        v += __shfl_xor_sync(FULL, v, 1);
        v += __shfl_xor_sync(FULL, v, 2);
        #pragma unroll
        for (int l = 0; l < L; ++l) e[l] = __shfl_sync(FULL, v, 4 * l);
    }

    // ---- Grid-stride row loop ----
    const float4* in4  = reinterpret_cast<const float4*>(input);
    float4*       out4 = reinterpret_cast<float4*>(out);
    const int stride = gridDim.x;
    const int D4 = D / 4;

    int row = blockIdx.x;
    int p = 1;
    float4 xa, xb;
    if (row < B) {
        xa = in4[(size_t)row * D4 + 2 * t];
        xb = in4[(size_t)row * D4 + 2 * t + 1];
    }

    for (; row < B; row += stride, p ^= 1) {
        // prefetch next row
        const int nrow = row + stride;
        float4 na, nb;
        if (nrow < B) {
            na = in4[(size_t)nrow * D4 + 2 * t];
            nb = in4[(size_t)nrow * D4 + 2 * t + 1];
        }

        // 6 dot partials over this thread's 8 columns
        float acc[L];
        #pragma unroll
        for (int l = 0; l < L; ++l) {
            acc[l] = xa.x * wa[l].x + xa.y * wa[l].y + xa.z * wa[l].z + xa.w * wa[l].w
                   + xb.x * wb[l].x + xb.y * wb[l].y + xb.z * wb[l].z + xb.w * wb[l].w;
        }

        // warp butterfly (every lane ends with all 6 warp sums)
        #pragma unroll
        for (int l = 0; l < L; ++l) {
            #pragma unroll
            for (int o = 16; o > 0; o >>= 1) acc[l] += __shfl_xor_sync(FULL, acc[l], o);
        }

        // one packed STS per warp: lane l<6 stores layer l's warp sum
        if (lane < L) red[p][lane * NW + warp] = pick6(acc, lane);
        __syncthreads();

        // cross-warp combine in one wavefront: 24 partials across lanes
        float c = 1.0f;
        {
            float v = (lane < L * NW) ? red[p][lane] : 0.f;
            v += __shfl_xor_sync(FULL, v, 1);
            v += __shfl_xor_sync(FULL, v, 2);       // lane 4l (+group) holds S_l
            #pragma unroll
            for (int l = 0; l < L; ++l) {
                float S = __shfl_sync(FULL, v, 4 * l);
                c = fmaf(c, 1.0f + S, e[l]);
            }
        }

        float4 oa, ob;
        oa.x = fmaf(c, xa.x, da.x); oa.y = fmaf(c, xa.y, da.y);
        oa.z = fmaf(c, xa.z, da.z); oa.w = fmaf(c, xa.w, da.w);
        ob.x = fmaf(c, xb.x, db.x); ob.y = fmaf(c, xb.y, db.y);
        ob.z = fmaf(c, xb.z, db.z); ob.w = fmaf(c, xb.w, db.w);
        out4[(size_t)row * D4 + 2 * t]     = oa;
        out4[(size_t)row * D4 + 2 * t + 1] = ob;

        xa = na; xb = nb;
    }
}

extern "C" void kernel_launch(void* const* d_in, const int* in_sizes, int n_in,
                              void* d_out, int out_size) {
    const float* input = (const float*)d_in[0];   // [B, D]
    const float* W     = (const float*)d_in[1];   // [L, D]
    const float* b     = (const float*)d_in[2];   // [L, D]
    float* out = (float*)d_out;

    int B = in_sizes[0] / D;

    int grid = 148 * 5;                 // one wave at 5 CTAs/SM
    if (grid > B) grid = B;

    cross_fused<<<grid, TPB>>>(input, W, b, out, B);
}